// round 15
// baseline (speedup 1.0000x reference)
#include <cuda_runtime.h>
#include <cuda_fp16.h>
#include <math.h>
#include <stdint.h>

#define ROWS  8192          // B*S
#define DM    768
#define DMLP  3072
#define QKVN  2304
#define NHEAD 12
#define DHEAD 64
#define SEQ   1024
#define NBH   96            // B * NHEAD
#define NSM_CTAS 296        // 148 SMs x 2 CTAs

// Q pre-scale: 1/sqrt(64) * log2(e)  -> scores land in log2 domain
#define QSCALE 0.1803368801111204f

// ---------------- scratch (device globals; no allocation allowed) ----------------
__device__ __half g_x16[ROWS * DM];          // LN1 / LN2 out (fp16, reused sequentially)
__device__ __half g_z16[ROWS * DM];          // attention out (fp16)
__device__ float  g_mid[ROWS * DM];
__device__ __half g_h16[ROWS * DMLP];        // MLP hidden (fp16)
__device__ __half g_wqkv[QKVN * DM];         // [N=2304][K=768] fp16
__device__ __half g_wo[DM * DM];             // [N=768][K=768] fp16
__device__ __half g_win[DMLP * DM];          // [N=3072][K=768] fp16
__device__ __half g_wout[DM * DMLP];         // [N=768][K=3072] fp16
__device__ float  g_bqkv[QKVN];
__device__ __half g_q16[NBH * SEQ * DHEAD];  // [b,h,s,d], pre-scaled QSCALE
__device__ __half g_k16[NBH * SEQ * DHEAD];
__device__ __half g_v16[NBH * SEQ * DHEAD];

// ---------------- helpers ----------------
__device__ __forceinline__ uint32_t smem_to_u32(const void* p) {
    uint32_t a;
    asm("{ .reg .u64 t; cvta.to.shared.u64 t, %1; cvt.u32.u64 %0, t; }" : "=r"(a) : "l"(p));
    return a;
}
__device__ __forceinline__ void cp_async16(uint32_t dst, const void* src) {
    asm volatile("cp.async.cg.shared.global [%0], [%1], 16;\n" :: "r"(dst), "l"(src));
}
#define CP_COMMIT() asm volatile("cp.async.commit_group;\n" ::: "memory")
#define CP_WAIT(n)  asm volatile("cp.async.wait_group %0;\n" :: "n"(n) : "memory")

__device__ __forceinline__ void ldsm_x4(uint32_t& r0, uint32_t& r1, uint32_t& r2, uint32_t& r3,
                                        uint32_t addr) {
    asm volatile("ldmatrix.sync.aligned.m8n8.x4.shared.b16 {%0,%1,%2,%3}, [%4];"
                 : "=r"(r0), "=r"(r1), "=r"(r2), "=r"(r3) : "r"(addr));
}
__device__ __forceinline__ void ldsm_x4_trans(uint32_t& r0, uint32_t& r1, uint32_t& r2,
                                              uint32_t& r3, uint32_t addr) {
    asm volatile("ldmatrix.sync.aligned.m8n8.x4.trans.shared.b16 {%0,%1,%2,%3}, [%4];"
                 : "=r"(r0), "=r"(r1), "=r"(r2), "=r"(r3) : "r"(addr));
}
__device__ __forceinline__ void mma_f16(float* c, const uint32_t* a, uint32_t b0, uint32_t b1) {
    asm volatile(
        "mma.sync.aligned.m16n8k16.row.col.f32.f16.f16.f32 "
        "{%0,%1,%2,%3}, {%4,%5,%6,%7}, {%8,%9}, {%0,%1,%2,%3};"
        : "+f"(c[0]), "+f"(c[1]), "+f"(c[2]), "+f"(c[3])
        : "r"(a[0]), "r"(a[1]), "r"(a[2]), "r"(a[3]), "r"(b0), "r"(b1));
}
__device__ __forceinline__ uint32_t pack_h2(float a, float b) {
    __half2 p = __floats2half2_rn(a, b);
    return *(uint32_t*)&p;
}
__device__ __forceinline__ float gelu_new_f(float x) {
    float x3 = x * x * x;
    float t  = tanhf(0.7978845608028654f * (x + 0.044715f * x3));
    return 0.5f * x * (1.0f + t);
}

// ---------------- fused prologue: LN1 + pack_wqkv + 3 weight transposes ----------------
#define NB_LN    ROWS
#define NB_PACK  ((QKVN * DM + 255) / 256)            // 6912
#define NB_TWO   ((DM / 32) * (DM / 32))              // 576
#define NB_TWIN  ((DMLP / 32) * (DM / 32))            // 2304
#define NB_TWOUT ((DM / 32) * (DMLP / 32))            // 2304
#define NB_PREP  (NB_LN + NB_PACK + NB_TWO + NB_TWIN + NB_TWOUT)

__global__ void prep_kernel(const float* __restrict__ resid_pre,
                            const float* __restrict__ ln1w, const float* __restrict__ ln1b,
                            const float* __restrict__ WQ, const float* __restrict__ WK,
                            const float* __restrict__ WV, const float* __restrict__ bQ,
                            const float* __restrict__ bK, const float* __restrict__ bV,
                            const float* __restrict__ WO, const float* __restrict__ Win,
                            const float* __restrict__ Wout) {
    __shared__ float tsh[32][33];
    __shared__ float shs[8], shss[8];
    int blk = blockIdx.x;
    int tid = threadIdx.x;

    if (blk < NB_LN) {
        int row = blk;
        const float* xr = resid_pre + (size_t)row * DM;
        float v0 = xr[tid], v1 = xr[tid + 256], v2 = xr[tid + 512];
        float s  = v0 + v1 + v2;
        float ss = v0 * v0 + v1 * v1 + v2 * v2;
#pragma unroll
        for (int o = 16; o > 0; o >>= 1) {
            s  += __shfl_xor_sync(0xffffffffu, s, o);
            ss += __shfl_xor_sync(0xffffffffu, ss, o);
        }
        int warp = tid >> 5, lane = tid & 31;
        if (lane == 0) { shs[warp] = s; shss[warp] = ss; }
        __syncthreads();
        if (tid < 32) {
            s  = (lane < 8) ? shs[lane] : 0.f;
            ss = (lane < 8) ? shss[lane] : 0.f;
#pragma unroll
            for (int o = 4; o > 0; o >>= 1) {
                s  += __shfl_xor_sync(0xffffffffu, s, o);
                ss += __shfl_xor_sync(0xffffffffu, ss, o);
            }
            if (lane == 0) { shs[0] = s; shss[0] = ss; }
        }
        __syncthreads();
        s = shs[0]; ss = shss[0];
        float mean = s * (1.f / DM);
        float var  = ss * (1.f / DM) - mean * mean;
        float rstd = rsqrtf(var + 1e-5f);
        __half* yr = g_x16 + (size_t)row * DM;
        yr[tid]       = __float2half((v0 - mean) * rstd * ln1w[tid]       + ln1b[tid]);
        yr[tid + 256] = __float2half((v1 - mean) * rstd * ln1w[tid + 256] + ln1b[tid + 256]);
        yr[tid + 512] = __float2half((v2 - mean) * rstd * ln1w[tid + 512] + ln1b[tid + 512]);
        return;
    }
    blk -= NB_LN;

    if (blk < NB_PACK) {
        int idx = blk * 256 + tid;
        if (idx < QKVN * DM) {
            int j = idx / DM;
            int d = idx - j * DM;
            int which = j / DM;
            int jj = j - which * DM;
            int h = jj >> 6, e = jj & 63;
            const float* W = (which == 0) ? WQ : (which == 1) ? WK : WV;
            g_wqkv[idx] = __float2half(W[(h * DM + d) * DHEAD + e]);
        }
        if (idx < QKVN) {
            g_bqkv[idx] = (idx < DM) ? bQ[idx] : (idx < 2 * DM) ? bK[idx - DM]
                                                                : bV[idx - 2 * DM];
        }
        return;
    }
    blk -= NB_PACK;

    const float* in;
    __half* outp;
    int R, C;
    if (blk < NB_TWO)          { in = WO;   outp = g_wo;   R = DM;   C = DM; }
    else if ((blk -= NB_TWO) < NB_TWIN) { in = Win;  outp = g_win;  R = DM;   C = DMLP; }
    else { blk -= NB_TWIN;       in = Wout; outp = g_wout; R = DMLP; C = DM; }
    int nbx = C / 32;
    int bx = (blk % nbx) * 32, by = (blk / nbx) * 32;
    int x = tid & 31, y = tid >> 5;
#pragma unroll
    for (int i = 0; i < 32; i += 8)
        tsh[y + i][x] = in[(size_t)(by + y + i) * C + bx + x];
    __syncthreads();
#pragma unroll
    for (int i = 0; i < 32; i += 8)
        outp[(size_t)(bx + y + i) * R + by + x] = __float2half(tsh[x][y + i]);
}

// ---------------- LayerNorm (emits fp16) — used for LN2 ----------------
__global__ void layernorm_kernel(const float* __restrict__ x, const float* __restrict__ w,
                                 const float* __restrict__ b, __half* __restrict__ yp) {
    int row = blockIdx.x;
    int tid = threadIdx.x;
    const float* xr = x + (size_t)row * DM;
    float v0 = xr[tid], v1 = xr[tid + 256], v2 = xr[tid + 512];
    float s  = v0 + v1 + v2;
    float ss = v0 * v0 + v1 * v1 + v2 * v2;
#pragma unroll
    for (int o = 16; o > 0; o >>= 1) {
        s  += __shfl_xor_sync(0xffffffffu, s, o);
        ss += __shfl_xor_sync(0xffffffffu, ss, o);
    }
    __shared__ float shs[8], shss[8];
    int warp = tid >> 5, lane = tid & 31;
    if (lane == 0) { shs[warp] = s; shss[warp] = ss; }
    __syncthreads();
    if (tid < 32) {
        s  = (lane < 8) ? shs[lane] : 0.f;
        ss = (lane < 8) ? shss[lane] : 0.f;
#pragma unroll
        for (int o = 4; o > 0; o >>= 1) {
            s  += __shfl_xor_sync(0xffffffffu, s, o);
            ss += __shfl_xor_sync(0xffffffffu, ss, o);
        }
        if (lane == 0) { shs[0] = s; shss[0] = ss; }
    }
    __syncthreads();
    s = shs[0]; ss = shss[0];
    float mean = s * (1.f / DM);
    float var  = ss * (1.f / DM) - mean * mean;
    float rstd = rsqrtf(var + 1e-5f);
    __half* yr = yp + (size_t)row * DM;
    yr[tid]       = __float2half((v0 - mean) * rstd * w[tid]       + b[tid]);
    yr[tid + 256] = __float2half((v1 - mean) * rstd * w[tid + 256] + b[tid + 256]);
    yr[tid + 512] = __float2half((v2 - mean) * rstd * w[tid + 512] + b[tid + 512]);
}

#define STG_BYTES 32768   // A 16KB + B 16KB per stage (K=64 fp16)

// ---------------- persistent fp16 HMMA GEMM: C[M,N] = A[M,K] x B[N,K]^T ----------------
// 128x128 CTA tile, 256 threads, warp tile 64x32, K=64/stage, 2 stages, 2 CTA/SM.
// Persistent: grid = min(ntiles, 296); each CTA grid-strides over tiles.
// Next tile's stages are prefetched BEFORE the current tile's epilogue.
// EPI: 1 = fp16 out +bias+GELU;  2 = fp32 out +bias+residual;
//      3 = QKV split to fp16 g_q16/g_k16/g_v16 (Q scaled QSCALE)
template <int EPI>
__global__ __launch_bounds__(256, 2) void gemm_f16_kernel(
    const __half* __restrict__ A, const __half* __restrict__ B,
    const float* __restrict__ bias, const float* __restrict__ Rres,
    void* __restrict__ Cout, int N, int K) {
    extern __shared__ char smem[];
    int tid = threadIdx.x, lane = tid & 31, wid = tid >> 5;
    int warp_m = (wid & 1) * 64;
    int warp_n = (wid >> 1) * 32;
    uint32_t sbase = smem_to_u32(smem);

    int ntx = N >> 7;                      // tiles along N
    int ntiles = (ROWS >> 7) * ntx;
    int T = K >> 6;

    int l7 = lane & 7;
    int a_r = ((lane >> 3) & 1) * 8 + l7;
    int a_k = lane >> 4;
    int b_r = (lane >> 4) * 8 + l7;
    int b_k = (lane >> 3) & 1;
    int quad = lane >> 2, tc2 = (lane & 3) * 2;

    const __half* Ab;
    const __half* Bb;

    auto load_stage = [&](int s, int kt) {
        uint32_t dstA = sbase + s * STG_BYTES;
        uint32_t dstB = dstA + 16384;
        const __half* Ag = Ab + kt * 64;
        const __half* Bg = Bb + kt * 64;
#pragma unroll
        for (int i = 0; i < 4; i++) {
            int idx = tid + i * 256;
            int r = idx >> 3, cc = idx & 7;
            uint32_t off = (uint32_t)(r * 128 + ((cc ^ (r & 7)) * 16));
            cp_async16(dstA + off, Ag + (size_t)r * K + cc * 8);
            cp_async16(dstB + off, Bg + (size_t)r * K + cc * 8);
        }
        CP_COMMIT();
    };

    int tile = blockIdx.x;
    if (tile >= ntiles) return;
    {
        int by = tile / ntx, bx = tile - by * ntx;
        Ab = A + (size_t)(by * 128) * K;
        Bb = B + (size_t)(bx * 128) * K;
    }
    load_stage(0, 0);
    load_stage(1, 1);

    while (true) {
        int by = tile / ntx, bx = tile - by * ntx;

        float c[4][4][4];
#pragma unroll
        for (int i = 0; i < 4; i++)
#pragma unroll
            for (int j = 0; j < 4; j++)
#pragma unroll
                for (int k = 0; k < 4; k++) c[i][j][k] = 0.f;

        for (int t = 0; t < T; t++) {
            if (t + 1 < T) { CP_WAIT(1); } else { CP_WAIT(0); }
            __syncthreads();

            uint32_t sA = sbase + (t & 1) * STG_BYTES;
            uint32_t sB = sA + 16384;
#pragma unroll
            for (int ks = 0; ks < 4; ks++) {
                uint32_t a[4][4];
#pragma unroll
                for (int i = 0; i < 4; i++) {
                    int row = warp_m + i * 16 + a_r;
                    uint32_t addr = sA + row * 128 + (((ks * 2 + a_k) ^ l7) * 16);
                    ldsm_x4(a[i][0], a[i][1], a[i][2], a[i][3], addr);
                }
                uint32_t b[2][4];
#pragma unroll
                for (int j = 0; j < 2; j++) {
                    int row = warp_n + j * 16 + b_r;
                    uint32_t addr = sB + row * 128 + (((ks * 2 + b_k) ^ l7) * 16);
                    ldsm_x4(b[j][0], b[j][1], b[j][2], b[j][3], addr);
                }
#pragma unroll
                for (int i = 0; i < 4; i++)
#pragma unroll
                    for (int jj = 0; jj < 4; jj++)
                        mma_f16(c[i][jj], a[i], b[jj >> 1][(jj & 1) * 2],
                                b[jj >> 1][(jj & 1) * 2 + 1]);
            }
            __syncthreads();
            if (t + 2 < T) load_stage(t & 1, t + 2);
        }

        // prefetch next tile's first two stages BEFORE epilogue (hides stores)
        int next = tile + gridDim.x;
        if (next < ntiles) {
            int nby = next / ntx, nbx = next - nby * ntx;
            Ab = A + (size_t)(nby * 128) * K;
            Bb = B + (size_t)(nbx * 128) * K;
            load_stage(0, 0);
            load_stage(1, 1);
        }

        // ---- epilogue for current tile ----
#pragma unroll
        for (int i = 0; i < 4; i++) {
#pragma unroll
            for (int jj = 0; jj < 4; jj++) {
                int row0 = by * 128 + warp_m + i * 16 + quad;
                int col  = bx * 128 + warp_n + jj * 8 + tc2;
                float bb0 = bias[col], bb1 = bias[col + 1];
                float v0 = c[i][jj][0] + bb0, v1 = c[i][jj][1] + bb1;
                float v2 = c[i][jj][2] + bb0, v3 = c[i][jj][3] + bb1;
                if (EPI == 3) {
                    int which = col / DM;
                    int rem = col - which * DM;
                    int h = rem >> 6, e = rem & 63;
                    __half* dsth = (which == 0) ? g_q16 : (which == 1) ? g_k16 : g_v16;
                    float sc = (which == 0) ? QSCALE : 1.0f;
#pragma unroll
                    for (int rr = 0; rr < 2; rr++) {
                        int rg = row0 + rr * 8;
                        int b_ = rg >> 10, s_ = rg & 1023;
                        size_t di = ((size_t)(b_ * NHEAD + h) * SEQ + s_) * DHEAD + e;
                        float x0 = (rr ? v2 : v0) * sc, x1 = (rr ? v3 : v1) * sc;
                        *(uint32_t*)(dsth + di) = pack_h2(x0, x1);
                    }
                } else if (EPI == 1) {
                    v0 = gelu_new_f(v0); v1 = gelu_new_f(v1);
                    v2 = gelu_new_f(v2); v3 = gelu_new_f(v3);
                    __half* Ch = (__half*)Cout;
                    *(uint32_t*)(Ch + (size_t)row0 * N + col)       = pack_h2(v0, v1);
                    *(uint32_t*)(Ch + (size_t)(row0 + 8) * N + col) = pack_h2(v2, v3);
                } else {
                    const float2 r0 = *(const float2*)(Rres + (size_t)row0 * N + col);
                    const float2 r1 = *(const float2*)(Rres + (size_t)(row0 + 8) * N + col);
                    v0 += r0.x; v1 += r0.y; v2 += r1.x; v3 += r1.y;
                    float* Cf = (float*)Cout;
                    *(float2*)(Cf + (size_t)row0 * N + col)       = make_float2(v0, v1);
                    *(float2*)(Cf + (size_t)(row0 + 8) * N + col) = make_float2(v2, v3);
                }
            }
        }
        if (next >= ntiles) break;
        tile = next;
    }
}

// ---------------- FA2 fp16 attention: 128-row q-tiles, log2-domain softmax ----------------
__global__ __launch_bounds__(256) void attn_kernel(__half* __restrict__ z) {
    extern __shared__ char sm[];                 // Q 16KB | {K 8KB, V 8KB} x2 stages
    int qt = blockIdx.x;
    int bh = blockIdx.y;
    int b = bh / NHEAD, h = bh - b * NHEAD;
    int tid = threadIdx.x, lane = tid & 31, w = tid >> 5;

    uint32_t sQ = smem_to_u32(sm);
    const __half* Qg = g_q16 + ((size_t)bh * SEQ + qt * 128) * DHEAD;
    const __half* Kg = g_k16 + (size_t)bh * SEQ * DHEAD;
    const __half* Vg = g_v16 + (size_t)bh * SEQ * DHEAD;

    {
#pragma unroll
        for (int i = 0; i < 4; i++) {
            int idx = tid + i * 256;
            int r = idx >> 3, cc = idx & 7;
            uint32_t off = (uint32_t)(r * 128 + ((cc ^ (r & 7)) << 4));
            cp_async16(sQ + off, Qg + (size_t)r * DHEAD + cc * 8);
        }
        CP_COMMIT();
    }
    auto load_kv = [&](int s, int jt) {
        uint32_t bK = sQ + 16384 + s * 16384;
        const __half* Ksrc = Kg + (size_t)jt * 64 * DHEAD;
        const __half* Vsrc = Vg + (size_t)jt * 64 * DHEAD;
#pragma unroll
        for (int i = 0; i < 2; i++) {
            int idx = tid + i * 256;
            int r = idx >> 3, cc = idx & 7;
            uint32_t off = (uint32_t)(r * 128 + ((cc ^ (r & 7)) << 4));
            cp_async16(bK + off, Ksrc + (size_t)r * DHEAD + cc * 8);
            cp_async16(bK + 8192 + off, Vsrc + (size_t)r * DHEAD + cc * 8);
        }
        CP_COMMIT();
    };

    load_kv(0, 0);
    CP_WAIT(0);
    __syncthreads();

    int l7 = lane & 7, lg = lane >> 3;
    uint32_t qa[4][4];
#pragma unroll
    for (int ks = 0; ks < 4; ks++) {
        int row = w * 16 + ((lg & 1) << 3) + l7;
        int chunk = ks * 2 + (lg >> 1);
        uint32_t addr = sQ + row * 128 + ((chunk ^ (row & 7)) << 4);
        ldsm_x4(qa[ks][0], qa[ks][1], qa[ks][2], qa[ks][3], addr);
    }

    int quad = lane >> 2, tc2 = (lane & 3) * 2;
    int wrow = qt * 128 + w * 16;
    float acc[8][4];
#pragma unroll
    for (int j = 0; j < 8; j++)
#pragma unroll
        for (int v = 0; v < 4; v++) acc[j][v] = 0.f;
    float m0 = -INFINITY, m1 = -INFINITY, l0 = 0.f, l1 = 0.f;

    int ntile = 2 * qt + 2;
    for (int jt = 0; jt < ntile; jt++) {
        if (jt + 1 < ntile) { load_kv((jt + 1) & 1, jt + 1); CP_WAIT(1); }
        else                { CP_WAIT(0); }
        __syncthreads();

        if (jt * 64 <= wrow + 15) {
            uint32_t sK = sQ + 16384 + (jt & 1) * 16384;
            uint32_t sV = sK + 8192;

            float c[8][4];
#pragma unroll
            for (int j = 0; j < 8; j++)
#pragma unroll
                for (int v = 0; v < 4; v++) c[j][v] = 0.f;
#pragma unroll
            for (int ks = 0; ks < 4; ks++) {
                uint32_t kb[4][4];
#pragma unroll
                for (int g = 0; g < 4; g++) {
                    int row = g * 16 + (lg >> 1) * 8 + l7;
                    int chunk = ks * 2 + (lg & 1);
                    uint32_t addr = sK + row * 128 + ((chunk ^ (row & 7)) << 4);
                    ldsm_x4(kb[g][0], kb[g][1], kb[g][2], kb[g][3], addr);
                }
#pragma unroll
                for (int j = 0; j < 8; j++)
                    mma_f16(c[j], qa[ks], kb[j >> 1][(j & 1) * 2],
                            kb[j >> 1][(j & 1) * 2 + 1]);
            }

            if ((jt + 1) * 64 - 1 > wrow) {
                int r0 = wrow + quad;
                int kbase = jt * 64;
#pragma unroll
                for (int j = 0; j < 8; j++) {
                    int kc = kbase + j * 8 + tc2;
                    if (kc > r0)     c[j][0] = -INFINITY;
                    if (kc + 1 > r0) c[j][1] = -INFINITY;
                    if (kc > r0 + 8)     c[j][2] = -INFINITY;
                    if (kc + 1 > r0 + 8) c[j][3] = -INFINITY;
                }
            }

            float mx0 = -INFINITY, mx1 = -INFINITY;
#pragma unroll
            for (int j = 0; j < 8; j++) {
                mx0 = fmaxf(mx0, fmaxf(c[j][0], c[j][1]));
                mx1 = fmaxf(mx1, fmaxf(c[j][2], c[j][3]));
            }
            mx0 = fmaxf(mx0, __shfl_xor_sync(0xffffffffu, mx0, 1));
            mx0 = fmaxf(mx0, __shfl_xor_sync(0xffffffffu, mx0, 2));
            mx1 = fmaxf(mx1, __shfl_xor_sync(0xffffffffu, mx1, 1));
            mx1 = fmaxf(mx1, __shfl_xor_sync(0xffffffffu, mx1, 2));
            float mn0 = fmaxf(m0, mx0), mn1 = fmaxf(m1, mx1);
            float corr0 = exp2f(m0 - mn0), corr1 = exp2f(m1 - mn1);
            l0 *= corr0; l1 *= corr1;
#pragma unroll
            for (int j = 0; j < 8; j++) {
                c[j][0] = exp2f(c[j][0] - mn0);
                c[j][1] = exp2f(c[j][1] - mn0);
                c[j][2] = exp2f(c[j][2] - mn1);
                c[j][3] = exp2f(c[j][3] - mn1);
                l0 += c[j][0] + c[j][1];
                l1 += c[j][2] + c[j][3];
#pragma unroll
                for (int v = 0; v < 4; v++)
                    acc[j][v] *= (v < 2) ? corr0 : corr1;
            }
            m0 = mn0; m1 = mn1;

#pragma unroll
            for (int t = 0; t < 4; t++) {
                uint32_t pa[4];
                pa[0] = pack_h2(c[2 * t][0], c[2 * t][1]);
                pa[1] = pack_h2(c[2 * t][2], c[2 * t][3]);
                pa[2] = pack_h2(c[2 * t + 1][0], c[2 * t + 1][1]);
                pa[3] = pack_h2(c[2 * t + 1][2], c[2 * t + 1][3]);
#pragma unroll
                for (int nb = 0; nb < 4; nb++) {
                    uint32_t vb[4];
                    int key = t * 16 + ((lg & 1) << 3) + l7;
                    int chunk = nb * 2 + (lg >> 1);
                    uint32_t addr = sV + key * 128 + ((chunk ^ (key & 7)) << 4);
                    ldsm_x4_trans(vb[0], vb[1], vb[2], vb[3], addr);
                    mma_f16(acc[nb * 2],     pa, vb[0], vb[1]);
                    mma_f16(acc[nb * 2 + 1], pa, vb[2], vb[3]);
                }
            }
        }
        __syncthreads();
    }

    l0 += __shfl_xor_sync(0xffffffffu, l0, 1);
    l0 += __shfl_xor_sync(0xffffffffu, l0, 2);
    l1 += __shfl_xor_sync(0xffffffffu, l1, 1);
    l1 += __shfl_xor_sync(0xffffffffu, l1, 2);
    float inv0 = 1.f / l0, inv1 = 1.f / l1;
    int r0g = b * SEQ + qt * 128 + w * 16 + quad;
#pragma unroll
    for (int j = 0; j < 8; j++) {
        int col = h * 64 + j * 8 + tc2;
        *(uint32_t*)(z + (size_t)r0g * DM + col) = pack_h2(acc[j][0] * inv0, acc[j][1] * inv0);
        *(uint32_t*)(z + (size_t)(r0g + 8) * DM + col) =
            pack_h2(acc[j][2] * inv1, acc[j][3] * inv1);
    }
}

// ---------------- launch ----------------
static inline int gemm_grid(int N) {
    int nt = (ROWS / 128) * (N / 128);
    return nt < NSM_CTAS ? nt : NSM_CTAS;
}

extern "C" void kernel_launch(void* const* d_in, const int* in_sizes, int n_in,
                              void* d_out, int out_size) {
    const float* resid_pre = (const float*)d_in[0];
    const float* W_Q  = (const float*)d_in[1];
    const float* W_K  = (const float*)d_in[2];
    const float* W_V  = (const float*)d_in[3];
    const float* W_O  = (const float*)d_in[4];
    const float* b_Q  = (const float*)d_in[5];
    const float* b_K  = (const float*)d_in[6];
    const float* b_V  = (const float*)d_in[7];
    const float* b_O  = (const float*)d_in[8];
    const float* ln1w = (const float*)d_in[9];
    const float* ln1b = (const float*)d_in[10];
    const float* ln2w = (const float*)d_in[11];
    const float* ln2b = (const float*)d_in[12];
    const float* W_in  = (const float*)d_in[13];
    const float* b_in  = (const float*)d_in[14];
    const float* W_out = (const float*)d_in[15];
    const float* b_out = (const float*)d_in[16];
    float* out = (float*)d_out;

    __half *x16, *z16, *h16, *wqkv, *wo, *win, *wout;
    float *mid, *bqkv;
    cudaGetSymbolAddress((void**)&x16,  g_x16);
    cudaGetSymbolAddress((void**)&z16,  g_z16);
    cudaGetSymbolAddress((void**)&h16,  g_h16);
    cudaGetSymbolAddress((void**)&mid,  g_mid);
    cudaGetSymbolAddress((void**)&wqkv, g_wqkv);
    cudaGetSymbolAddress((void**)&wo,   g_wo);
    cudaGetSymbolAddress((void**)&win,  g_win);
    cudaGetSymbolAddress((void**)&wout, g_wout);
    cudaGetSymbolAddress((void**)&bqkv, g_bqkv);

    const int SMEM_G = 2 * STG_BYTES;           // 64KB, 2 CTA/SM
    const int SMEM_A = 16384 + 2 * 16384;       // 48KB attention
    cudaFuncSetAttribute(gemm_f16_kernel<1>, cudaFuncAttributeMaxDynamicSharedMemorySize, SMEM_G);
    cudaFuncSetAttribute(gemm_f16_kernel<2>, cudaFuncAttributeMaxDynamicSharedMemorySize, SMEM_G);
    cudaFuncSetAttribute(gemm_f16_kernel<3>, cudaFuncAttributeMaxDynamicSharedMemorySize, SMEM_G);
    cudaFuncSetAttribute(attn_kernel, cudaFuncAttributeMaxDynamicSharedMemorySize, SMEM_A);

    // 1) fused prologue: LN1 + all weight packing in ONE launch
    prep_kernel<<<NB_PREP, 256>>>(resid_pre, ln1w, ln1b, W_Q, W_K, W_V, b_Q, b_K, b_V,
                                  W_O, W_in, W_out);
    // 2) fused QKV projection (persistent fp16 mma) -> fp16 Q/K/V [b,h,s,d]
    gemm_f16_kernel<3><<<gemm_grid(QKVN), 256, SMEM_G>>>(x16, wqkv, bqkv,
                                                         nullptr, nullptr, QKVN, DM);
    // 3) tensor-core causal attention -> z (fp16)
    attn_kernel<<<dim3(SEQ / 128, NBH), 256, SMEM_A>>>(z16);
    // 4) O projection (persistent) + bias + residual -> mid (fp32)
    gemm_f16_kernel<2><<<gemm_grid(DM), 256, SMEM_G>>>(z16, wo, b_O, resid_pre,
                                                       mid, DM, DM);
    // 5) LN2 -> fp16
    layernorm_kernel<<<ROWS, 256>>>(mid, ln2w, ln2b, x16);
    // 6) MLP in + bias + GELU (persistent) -> fp16 hidden
    gemm_f16_kernel<1><<<gemm_grid(DMLP), 256, SMEM_G>>>(x16, win, b_in, nullptr,
                                                         h16, DMLP, DM);
    // 7) MLP out (persistent) + bias + residual -> out (fp32)
    gemm_f16_kernel<2><<<gemm_grid(DM), 256, SMEM_G>>>(h16, wout, b_out, mid,
                                                       out, DM, DMLP);
}

// round 16
// speedup vs baseline: 1.5467x; 1.5467x over previous
#include <cuda_runtime.h>
#include <cuda_fp16.h>
#include <math.h>
#include <stdint.h>

#define ROWS  8192          // B*S
#define DM    768
#define DMLP  3072
#define QKVN  2304
#define NHEAD 12
#define DHEAD 64
#define SEQ   1024
#define NBH   96            // B * NHEAD

// Q pre-scale: 1/sqrt(64) * log2(e)  -> scores land in log2 domain
#define QSCALE 0.1803368801111204f

// ---------------- scratch (device globals; no allocation allowed) ----------------
__device__ __half g_x16[ROWS * DM];          // LN1 / LN2 out (fp16, reused sequentially)
__device__ __half g_z16[ROWS * DM];          // attention out (fp16)
__device__ float  g_mid[ROWS * DM];
__device__ __half g_h16[ROWS * DMLP];        // MLP hidden (fp16)
__device__ __half g_wqkv[QKVN * DM];         // [N=2304][K=768] fp16
__device__ __half g_wo[DM * DM];             // [N=768][K=768] fp16
__device__ __half g_win[DMLP * DM];          // [N=3072][K=768] fp16
__device__ __half g_wout[DM * DMLP];         // [N=768][K=3072] fp16
__device__ float  g_bqkv[QKVN];
__device__ __half g_q16[NBH * SEQ * DHEAD];  // [b,h,s,d], pre-scaled QSCALE
__device__ __half g_k16[NBH * SEQ * DHEAD];
__device__ __half g_v16[NBH * SEQ * DHEAD];

// ---------------- helpers ----------------
__device__ __forceinline__ uint32_t smem_to_u32(const void* p) {
    uint32_t a;
    asm("{ .reg .u64 t; cvta.to.shared.u64 t, %1; cvt.u32.u64 %0, t; }" : "=r"(a) : "l"(p));
    return a;
}
__device__ __forceinline__ void cp_async16(uint32_t dst, const void* src) {
    asm volatile("cp.async.cg.shared.global [%0], [%1], 16;\n" :: "r"(dst), "l"(src));
}
#define CP_COMMIT() asm volatile("cp.async.commit_group;\n" ::: "memory")
#define CP_WAIT(n)  asm volatile("cp.async.wait_group %0;\n" :: "n"(n) : "memory")

__device__ __forceinline__ void ldsm_x4(uint32_t& r0, uint32_t& r1, uint32_t& r2, uint32_t& r3,
                                        uint32_t addr) {
    asm volatile("ldmatrix.sync.aligned.m8n8.x4.shared.b16 {%0,%1,%2,%3}, [%4];"
                 : "=r"(r0), "=r"(r1), "=r"(r2), "=r"(r3) : "r"(addr));
}
__device__ __forceinline__ void ldsm_x4_trans(uint32_t& r0, uint32_t& r1, uint32_t& r2,
                                              uint32_t& r3, uint32_t addr) {
    asm volatile("ldmatrix.sync.aligned.m8n8.x4.trans.shared.b16 {%0,%1,%2,%3}, [%4];"
                 : "=r"(r0), "=r"(r1), "=r"(r2), "=r"(r3) : "r"(addr));
}
__device__ __forceinline__ void mma_f16(float* c, const uint32_t* a, uint32_t b0, uint32_t b1) {
    asm volatile(
        "mma.sync.aligned.m16n8k16.row.col.f32.f16.f16.f32 "
        "{%0,%1,%2,%3}, {%4,%5,%6,%7}, {%8,%9}, {%0,%1,%2,%3};"
        : "+f"(c[0]), "+f"(c[1]), "+f"(c[2]), "+f"(c[3])
        : "r"(a[0]), "r"(a[1]), "r"(a[2]), "r"(a[3]), "r"(b0), "r"(b1));
}
__device__ __forceinline__ uint32_t pack_h2(float a, float b) {
    __half2 p = __floats2half2_rn(a, b);
    return *(uint32_t*)&p;
}
__device__ __forceinline__ float gelu_new_f(float x) {
    float x3 = x * x * x;
    float t  = tanhf(0.7978845608028654f * (x + 0.044715f * x3));
    return 0.5f * x * (1.0f + t);
}

// ---------------- fused prologue: LN1 + pack_wqkv + 3 weight transposes ----------------
#define NB_LN    ROWS
#define NB_PACK  ((QKVN * DM + 255) / 256)            // 6912
#define NB_TWO   ((DM / 32) * (DM / 32))              // 576
#define NB_TWIN  ((DMLP / 32) * (DM / 32))            // 2304
#define NB_TWOUT ((DM / 32) * (DMLP / 32))            // 2304
#define NB_PREP  (NB_LN + NB_PACK + NB_TWO + NB_TWIN + NB_TWOUT)

__global__ void prep_kernel(const float* __restrict__ resid_pre,
                            const float* __restrict__ ln1w, const float* __restrict__ ln1b,
                            const float* __restrict__ WQ, const float* __restrict__ WK,
                            const float* __restrict__ WV, const float* __restrict__ bQ,
                            const float* __restrict__ bK, const float* __restrict__ bV,
                            const float* __restrict__ WO, const float* __restrict__ Win,
                            const float* __restrict__ Wout) {
    __shared__ float tsh[32][33];
    __shared__ float shs[8], shss[8];
    int blk = blockIdx.x;
    int tid = threadIdx.x;

    if (blk < NB_LN) {
        int row = blk;
        const float* xr = resid_pre + (size_t)row * DM;
        float v0 = xr[tid], v1 = xr[tid + 256], v2 = xr[tid + 512];
        float s  = v0 + v1 + v2;
        float ss = v0 * v0 + v1 * v1 + v2 * v2;
#pragma unroll
        for (int o = 16; o > 0; o >>= 1) {
            s  += __shfl_xor_sync(0xffffffffu, s, o);
            ss += __shfl_xor_sync(0xffffffffu, ss, o);
        }
        int warp = tid >> 5, lane = tid & 31;
        if (lane == 0) { shs[warp] = s; shss[warp] = ss; }
        __syncthreads();
        if (tid < 32) {
            s  = (lane < 8) ? shs[lane] : 0.f;
            ss = (lane < 8) ? shss[lane] : 0.f;
#pragma unroll
            for (int o = 4; o > 0; o >>= 1) {
                s  += __shfl_xor_sync(0xffffffffu, s, o);
                ss += __shfl_xor_sync(0xffffffffu, ss, o);
            }
            if (lane == 0) { shs[0] = s; shss[0] = ss; }
        }
        __syncthreads();
        s = shs[0]; ss = shss[0];
        float mean = s * (1.f / DM);
        float var  = ss * (1.f / DM) - mean * mean;
        float rstd = rsqrtf(var + 1e-5f);
        __half* yr = g_x16 + (size_t)row * DM;
        yr[tid]       = __float2half((v0 - mean) * rstd * ln1w[tid]       + ln1b[tid]);
        yr[tid + 256] = __float2half((v1 - mean) * rstd * ln1w[tid + 256] + ln1b[tid + 256]);
        yr[tid + 512] = __float2half((v2 - mean) * rstd * ln1w[tid + 512] + ln1b[tid + 512]);
        return;
    }
    blk -= NB_LN;

    if (blk < NB_PACK) {
        int idx = blk * 256 + tid;
        if (idx < QKVN * DM) {
            int j = idx / DM;
            int d = idx - j * DM;
            int which = j / DM;
            int jj = j - which * DM;
            int h = jj >> 6, e = jj & 63;
            const float* W = (which == 0) ? WQ : (which == 1) ? WK : WV;
            g_wqkv[idx] = __float2half(W[(h * DM + d) * DHEAD + e]);
        }
        if (idx < QKVN) {
            g_bqkv[idx] = (idx < DM) ? bQ[idx] : (idx < 2 * DM) ? bK[idx - DM]
                                                                : bV[idx - 2 * DM];
        }
        return;
    }
    blk -= NB_PACK;

    const float* in;
    __half* outp;
    int R, C;
    if (blk < NB_TWO)          { in = WO;   outp = g_wo;   R = DM;   C = DM; }
    else if ((blk -= NB_TWO) < NB_TWIN) { in = Win;  outp = g_win;  R = DM;   C = DMLP; }
    else { blk -= NB_TWIN;       in = Wout; outp = g_wout; R = DMLP; C = DM; }
    int nbx = C / 32;
    int bx = (blk % nbx) * 32, by = (blk / nbx) * 32;
    int x = tid & 31, y = tid >> 5;
#pragma unroll
    for (int i = 0; i < 32; i += 8)
        tsh[y + i][x] = in[(size_t)(by + y + i) * C + bx + x];
    __syncthreads();
#pragma unroll
    for (int i = 0; i < 32; i += 8)
        outp[(size_t)(bx + y + i) * R + by + x] = __float2half(tsh[x][y + i]);
}

// ---------------- LayerNorm (emits fp16) — used for LN2 ----------------
__global__ void layernorm_kernel(const float* __restrict__ x, const float* __restrict__ w,
                                 const float* __restrict__ b, __half* __restrict__ yp) {
    int row = blockIdx.x;
    int tid = threadIdx.x;
    const float* xr = x + (size_t)row * DM;
    float v0 = xr[tid], v1 = xr[tid + 256], v2 = xr[tid + 512];
    float s  = v0 + v1 + v2;
    float ss = v0 * v0 + v1 * v1 + v2 * v2;
#pragma unroll
    for (int o = 16; o > 0; o >>= 1) {
        s  += __shfl_xor_sync(0xffffffffu, s, o);
        ss += __shfl_xor_sync(0xffffffffu, ss, o);
    }
    __shared__ float shs[8], shss[8];
    int warp = tid >> 5, lane = tid & 31;
    if (lane == 0) { shs[warp] = s; shss[warp] = ss; }
    __syncthreads();
    if (tid < 32) {
        s  = (lane < 8) ? shs[lane] : 0.f;
        ss = (lane < 8) ? shss[lane] : 0.f;
#pragma unroll
        for (int o = 4; o > 0; o >>= 1) {
            s  += __shfl_xor_sync(0xffffffffu, s, o);
            ss += __shfl_xor_sync(0xffffffffu, ss, o);
        }
        if (lane == 0) { shs[0] = s; shss[0] = ss; }
    }
    __syncthreads();
    s = shs[0]; ss = shss[0];
    float mean = s * (1.f / DM);
    float var  = ss * (1.f / DM) - mean * mean;
    float rstd = rsqrtf(var + 1e-5f);
    __half* yr = yp + (size_t)row * DM;
    yr[tid]       = __float2half((v0 - mean) * rstd * w[tid]       + b[tid]);
    yr[tid + 256] = __float2half((v1 - mean) * rstd * w[tid + 256] + b[tid + 256]);
    yr[tid + 512] = __float2half((v2 - mean) * rstd * w[tid + 512] + b[tid + 512]);
}

#define STG_BYTES 32768   // A 16KB + B 16KB per stage (K=64 fp16)

// ---------------- fp16 HMMA GEMM: C[M,N] = A[M,K] x B[N,K]^T (R12 config) ----------------
// 128x128 CTA tile, 256 threads, warp tile 64x32, K=64/stage, 2 stages, 2 CTA/SM.
// EPI: 1 = fp16 out +bias+GELU;  2 = fp32 out +bias+residual;
//      3 = QKV split to fp16 g_q16/g_k16/g_v16 (Q scaled QSCALE)
template <int EPI>
__global__ __launch_bounds__(256, 2) void gemm_f16_kernel(
    const __half* __restrict__ A, const __half* __restrict__ B,
    const float* __restrict__ bias, const float* __restrict__ Rres,
    void* __restrict__ Cout, int N, int K) {
    extern __shared__ char smem[];
    int tid = threadIdx.x, lane = tid & 31, wid = tid >> 5;
    int bx = blockIdx.x, by = blockIdx.y;
    int warp_m = (wid & 1) * 64;
    int warp_n = (wid >> 1) * 32;

    const __half* Ab = A + (size_t)(by * 128) * K;
    const __half* Bb = B + (size_t)(bx * 128) * K;
    uint32_t sbase = smem_to_u32(smem);

    float c[4][4][4];
#pragma unroll
    for (int i = 0; i < 4; i++)
#pragma unroll
        for (int j = 0; j < 4; j++)
#pragma unroll
            for (int k = 0; k < 4; k++) c[i][j][k] = 0.f;

    int T = K >> 6;

    auto load_stage = [&](int s, int kt) {
        uint32_t dstA = sbase + s * STG_BYTES;
        uint32_t dstB = dstA + 16384;
        const __half* Ag = Ab + kt * 64;
        const __half* Bg = Bb + kt * 64;
#pragma unroll
        for (int i = 0; i < 4; i++) {
            int idx = tid + i * 256;
            int r = idx >> 3, cc = idx & 7;
            uint32_t off = (uint32_t)(r * 128 + ((cc ^ (r & 7)) * 16));
            cp_async16(dstA + off, Ag + (size_t)r * K + cc * 8);
            cp_async16(dstB + off, Bg + (size_t)r * K + cc * 8);
        }
        CP_COMMIT();
    };

    load_stage(0, 0);
    load_stage(1, 1);

    int l7 = lane & 7;
    int a_r = ((lane >> 3) & 1) * 8 + l7;
    int a_k = lane >> 4;
    int b_r = (lane >> 4) * 8 + l7;
    int b_k = (lane >> 3) & 1;

    for (int t = 0; t < T; t++) {
        if (t + 1 < T) { CP_WAIT(1); } else { CP_WAIT(0); }
        __syncthreads();

        uint32_t sA = sbase + (t & 1) * STG_BYTES;
        uint32_t sB = sA + 16384;
#pragma unroll
        for (int ks = 0; ks < 4; ks++) {
            uint32_t a[4][4];
#pragma unroll
            for (int i = 0; i < 4; i++) {
                int row = warp_m + i * 16 + a_r;
                uint32_t addr = sA + row * 128 + (((ks * 2 + a_k) ^ l7) * 16);
                ldsm_x4(a[i][0], a[i][1], a[i][2], a[i][3], addr);
            }
            uint32_t b[2][4];
#pragma unroll
            for (int j = 0; j < 2; j++) {
                int row = warp_n + j * 16 + b_r;
                uint32_t addr = sB + row * 128 + (((ks * 2 + b_k) ^ l7) * 16);
                ldsm_x4(b[j][0], b[j][1], b[j][2], b[j][3], addr);
            }
#pragma unroll
            for (int i = 0; i < 4; i++)
#pragma unroll
                for (int jj = 0; jj < 4; jj++)
                    mma_f16(c[i][jj], a[i], b[jj >> 1][(jj & 1) * 2],
                            b[jj >> 1][(jj & 1) * 2 + 1]);
        }
        __syncthreads();
        if (t + 2 < T) load_stage(t & 1, t + 2);
    }

    int quad = lane >> 2, tc2 = (lane & 3) * 2;
#pragma unroll
    for (int i = 0; i < 4; i++) {
#pragma unroll
        for (int jj = 0; jj < 4; jj++) {
            int row0 = by * 128 + warp_m + i * 16 + quad;
            int col  = bx * 128 + warp_n + jj * 8 + tc2;
            float bb0 = bias[col], bb1 = bias[col + 1];
            float v0 = c[i][jj][0] + bb0, v1 = c[i][jj][1] + bb1;
            float v2 = c[i][jj][2] + bb0, v3 = c[i][jj][3] + bb1;
            if (EPI == 3) {
                int which = col / DM;
                int rem = col - which * DM;
                int h = rem >> 6, e = rem & 63;
                __half* dsth = (which == 0) ? g_q16 : (which == 1) ? g_k16 : g_v16;
                float sc = (which == 0) ? QSCALE : 1.0f;
#pragma unroll
                for (int rr = 0; rr < 2; rr++) {
                    int rg = row0 + rr * 8;
                    int b_ = rg >> 10, s_ = rg & 1023;
                    size_t di = ((size_t)(b_ * NHEAD + h) * SEQ + s_) * DHEAD + e;
                    float x0 = (rr ? v2 : v0) * sc, x1 = (rr ? v3 : v1) * sc;
                    *(uint32_t*)(dsth + di) = pack_h2(x0, x1);
                }
            } else if (EPI == 1) {
                v0 = gelu_new_f(v0); v1 = gelu_new_f(v1);
                v2 = gelu_new_f(v2); v3 = gelu_new_f(v3);
                __half* Ch = (__half*)Cout;
                *(uint32_t*)(Ch + (size_t)row0 * N + col)       = pack_h2(v0, v1);
                *(uint32_t*)(Ch + (size_t)(row0 + 8) * N + col) = pack_h2(v2, v3);
            } else {
                const float2 r0 = *(const float2*)(Rres + (size_t)row0 * N + col);
                const float2 r1 = *(const float2*)(Rres + (size_t)(row0 + 8) * N + col);
                v0 += r0.x; v1 += r0.y; v2 += r1.x; v3 += r1.y;
                float* Cf = (float*)Cout;
                *(float2*)(Cf + (size_t)row0 * N + col)       = make_float2(v0, v1);
                *(float2*)(Cf + (size_t)(row0 + 8) * N + col) = make_float2(v2, v3);
            }
        }
    }
}

// ---------------- FA2 fp16 attention: 128-row q-tiles, log2-domain softmax ----------------
// 3-stage KV pipeline (two tiles in flight), longest q-tiles launched first.
__global__ __launch_bounds__(256) void attn_kernel(__half* __restrict__ z) {
    extern __shared__ char sm[];                 // Q 16KB | {K 8KB, V 8KB} x3 stages
    int qt = gridDim.x - 1 - blockIdx.x;         // longest-first scheduling
    int bh = blockIdx.y;
    int b = bh / NHEAD, h = bh - b * NHEAD;
    int tid = threadIdx.x, lane = tid & 31, w = tid >> 5;

    uint32_t sQ = smem_to_u32(sm);
    const __half* Qg = g_q16 + ((size_t)bh * SEQ + qt * 128) * DHEAD;
    const __half* Kg = g_k16 + (size_t)bh * SEQ * DHEAD;
    const __half* Vg = g_v16 + (size_t)bh * SEQ * DHEAD;

    {
#pragma unroll
        for (int i = 0; i < 4; i++) {
            int idx = tid + i * 256;
            int r = idx >> 3, cc = idx & 7;
            uint32_t off = (uint32_t)(r * 128 + ((cc ^ (r & 7)) << 4));
            cp_async16(sQ + off, Qg + (size_t)r * DHEAD + cc * 8);
        }
        CP_COMMIT();
    }
    auto load_kv = [&](int s, int jt) {
        uint32_t bK = sQ + 16384 + s * 16384;
        const __half* Ksrc = Kg + (size_t)jt * 64 * DHEAD;
        const __half* Vsrc = Vg + (size_t)jt * 64 * DHEAD;
#pragma unroll
        for (int i = 0; i < 2; i++) {
            int idx = tid + i * 256;
            int r = idx >> 3, cc = idx & 7;
            uint32_t off = (uint32_t)(r * 128 + ((cc ^ (r & 7)) << 4));
            cp_async16(bK + off, Ksrc + (size_t)r * DHEAD + cc * 8);
            cp_async16(bK + 8192 + off, Vsrc + (size_t)r * DHEAD + cc * 8);
        }
        CP_COMMIT();
    };

    int ntile = 2 * qt + 2;
    load_kv(0, 0);
    if (ntile > 1) load_kv(1, 1);
    // wait for Q + KV tile 0 (groups in flight after: at most 1)
    CP_WAIT(1);
    __syncthreads();

    int l7 = lane & 7, lg = lane >> 3;
    uint32_t qa[4][4];
#pragma unroll
    for (int ks = 0; ks < 4; ks++) {
        int row = w * 16 + ((lg & 1) << 3) + l7;
        int chunk = ks * 2 + (lg >> 1);
        uint32_t addr = sQ + row * 128 + ((chunk ^ (row & 7)) << 4);
        ldsm_x4(qa[ks][0], qa[ks][1], qa[ks][2], qa[ks][3], addr);
    }

    int quad = lane >> 2, tc2 = (lane & 3) * 2;
    int wrow = qt * 128 + w * 16;
    float acc[8][4];
#pragma unroll
    for (int j = 0; j < 8; j++)
#pragma unroll
        for (int v = 0; v < 4; v++) acc[j][v] = 0.f;
    float m0 = -INFINITY, m1 = -INFINITY, l0 = 0.f, l1 = 0.f;

    for (int jt = 0; jt < ntile; jt++) {
        // issue jt+2's load, then wait so jt's data is resident:
        // groups pending afterward = {jt+1, jt+2} -> CP_WAIT(2)
        if (jt + 2 < ntile) { load_kv((jt + 2) % 3, jt + 2); CP_WAIT(2); }
        else if (jt + 1 < ntile) { CP_WAIT(1); }
        else                     { CP_WAIT(0); }
        __syncthreads();

        if (jt * 64 <= wrow + 15) {
            uint32_t sK = sQ + 16384 + (jt % 3) * 16384;
            uint32_t sV = sK + 8192;

            float c[8][4];
#pragma unroll
            for (int j = 0; j < 8; j++)
#pragma unroll
                for (int v = 0; v < 4; v++) c[j][v] = 0.f;
#pragma unroll
            for (int ks = 0; ks < 4; ks++) {
                uint32_t kb[4][4];
#pragma unroll
                for (int g = 0; g < 4; g++) {
                    int row = g * 16 + (lg >> 1) * 8 + l7;
                    int chunk = ks * 2 + (lg & 1);
                    uint32_t addr = sK + row * 128 + ((chunk ^ (row & 7)) << 4);
                    ldsm_x4(kb[g][0], kb[g][1], kb[g][2], kb[g][3], addr);
                }
#pragma unroll
                for (int j = 0; j < 8; j++)
                    mma_f16(c[j], qa[ks], kb[j >> 1][(j & 1) * 2],
                            kb[j >> 1][(j & 1) * 2 + 1]);
            }

            if ((jt + 1) * 64 - 1 > wrow) {
                int r0 = wrow + quad;
                int kbase = jt * 64;
#pragma unroll
                for (int j = 0; j < 8; j++) {
                    int kc = kbase + j * 8 + tc2;
                    if (kc > r0)     c[j][0] = -INFINITY;
                    if (kc + 1 > r0) c[j][1] = -INFINITY;
                    if (kc > r0 + 8)     c[j][2] = -INFINITY;
                    if (kc + 1 > r0 + 8) c[j][3] = -INFINITY;
                }
            }

            float mx0 = -INFINITY, mx1 = -INFINITY;
#pragma unroll
            for (int j = 0; j < 8; j++) {
                mx0 = fmaxf(mx0, fmaxf(c[j][0], c[j][1]));
                mx1 = fmaxf(mx1, fmaxf(c[j][2], c[j][3]));
            }
            mx0 = fmaxf(mx0, __shfl_xor_sync(0xffffffffu, mx0, 1));
            mx0 = fmaxf(mx0, __shfl_xor_sync(0xffffffffu, mx0, 2));
            mx1 = fmaxf(mx1, __shfl_xor_sync(0xffffffffu, mx1, 1));
            mx1 = fmaxf(mx1, __shfl_xor_sync(0xffffffffu, mx1, 2));
            float mn0 = fmaxf(m0, mx0), mn1 = fmaxf(m1, mx1);
            float corr0 = exp2f(m0 - mn0), corr1 = exp2f(m1 - mn1);
            l0 *= corr0; l1 *= corr1;
#pragma unroll
            for (int j = 0; j < 8; j++) {
                c[j][0] = exp2f(c[j][0] - mn0);
                c[j][1] = exp2f(c[j][1] - mn0);
                c[j][2] = exp2f(c[j][2] - mn1);
                c[j][3] = exp2f(c[j][3] - mn1);
                l0 += c[j][0] + c[j][1];
                l1 += c[j][2] + c[j][3];
#pragma unroll
                for (int v = 0; v < 4; v++)
                    acc[j][v] *= (v < 2) ? corr0 : corr1;
            }
            m0 = mn0; m1 = mn1;

#pragma unroll
            for (int t = 0; t < 4; t++) {
                uint32_t pa[4];
                pa[0] = pack_h2(c[2 * t][0], c[2 * t][1]);
                pa[1] = pack_h2(c[2 * t][2], c[2 * t][3]);
                pa[2] = pack_h2(c[2 * t + 1][0], c[2 * t + 1][1]);
                pa[3] = pack_h2(c[2 * t + 1][2], c[2 * t + 1][3]);
#pragma unroll
                for (int nb = 0; nb < 4; nb++) {
                    uint32_t vb[4];
                    int key = t * 16 + ((lg & 1) << 3) + l7;
                    int chunk = nb * 2 + (lg >> 1);
                    uint32_t addr = sV + key * 128 + ((chunk ^ (key & 7)) << 4);
                    ldsm_x4_trans(vb[0], vb[1], vb[2], vb[3], addr);
                    mma_f16(acc[nb * 2],     pa, vb[0], vb[1]);
                    mma_f16(acc[nb * 2 + 1], pa, vb[2], vb[3]);
                }
            }
        }
        __syncthreads();
    }

    l0 += __shfl_xor_sync(0xffffffffu, l0, 1);
    l0 += __shfl_xor_sync(0xffffffffu, l0, 2);
    l1 += __shfl_xor_sync(0xffffffffu, l1, 1);
    l1 += __shfl_xor_sync(0xffffffffu, l1, 2);
    float inv0 = 1.f / l0, inv1 = 1.f / l1;
    int r0g = b * SEQ + qt * 128 + w * 16 + quad;
#pragma unroll
    for (int j = 0; j < 8; j++) {
        int col = h * 64 + j * 8 + tc2;
        *(uint32_t*)(z + (size_t)r0g * DM + col) = pack_h2(acc[j][0] * inv0, acc[j][1] * inv0);
        *(uint32_t*)(z + (size_t)(r0g + 8) * DM + col) =
            pack_h2(acc[j][2] * inv1, acc[j][3] * inv1);
    }
}

// ---------------- launch ----------------
extern "C" void kernel_launch(void* const* d_in, const int* in_sizes, int n_in,
                              void* d_out, int out_size) {
    const float* resid_pre = (const float*)d_in[0];
    const float* W_Q  = (const float*)d_in[1];
    const float* W_K  = (const float*)d_in[2];
    const float* W_V  = (const float*)d_in[3];
    const float* W_O  = (const float*)d_in[4];
    const float* b_Q  = (const float*)d_in[5];
    const float* b_K  = (const float*)d_in[6];
    const float* b_V  = (const float*)d_in[7];
    const float* b_O  = (const float*)d_in[8];
    const float* ln1w = (const float*)d_in[9];
    const float* ln1b = (const float*)d_in[10];
    const float* ln2w = (const float*)d_in[11];
    const float* ln2b = (const float*)d_in[12];
    const float* W_in  = (const float*)d_in[13];
    const float* b_in  = (const float*)d_in[14];
    const float* W_out = (const float*)d_in[15];
    const float* b_out = (const float*)d_in[16];
    float* out = (float*)d_out;

    __half *x16, *z16, *h16, *wqkv, *wo, *win, *wout;
    float *mid, *bqkv;
    cudaGetSymbolAddress((void**)&x16,  g_x16);
    cudaGetSymbolAddress((void**)&z16,  g_z16);
    cudaGetSymbolAddress((void**)&h16,  g_h16);
    cudaGetSymbolAddress((void**)&mid,  g_mid);
    cudaGetSymbolAddress((void**)&wqkv, g_wqkv);
    cudaGetSymbolAddress((void**)&wo,   g_wo);
    cudaGetSymbolAddress((void**)&win,  g_win);
    cudaGetSymbolAddress((void**)&wout, g_wout);
    cudaGetSymbolAddress((void**)&bqkv, g_bqkv);

    const int SMEM_G = 2 * STG_BYTES;           // 64KB, 2 CTA/SM
    const int SMEM_A = 16384 + 3 * 16384;       // 64KB attention (3-stage KV)
    cudaFuncSetAttribute(gemm_f16_kernel<1>, cudaFuncAttributeMaxDynamicSharedMemorySize, SMEM_G);
    cudaFuncSetAttribute(gemm_f16_kernel<2>, cudaFuncAttributeMaxDynamicSharedMemorySize, SMEM_G);
    cudaFuncSetAttribute(gemm_f16_kernel<3>, cudaFuncAttributeMaxDynamicSharedMemorySize, SMEM_G);
    cudaFuncSetAttribute(attn_kernel, cudaFuncAttributeMaxDynamicSharedMemorySize, SMEM_A);

    // 1) fused prologue: LN1 + all weight packing in ONE launch
    prep_kernel<<<NB_PREP, 256>>>(resid_pre, ln1w, ln1b, W_Q, W_K, W_V, b_Q, b_K, b_V,
                                  W_O, W_in, W_out);
    // 2) fused QKV projection (fp16 mma) -> fp16 Q/K/V [b,h,s,d], Q in log2-softmax scale
    gemm_f16_kernel<3><<<dim3(QKVN / 128, ROWS / 128), 256, SMEM_G>>>(x16, wqkv, bqkv,
                                                                      nullptr, nullptr, QKVN, DM);
    // 3) tensor-core causal attention -> z (fp16)
    attn_kernel<<<dim3(SEQ / 128, NBH), 256, SMEM_A>>>(z16);
    // 4) O projection (fp16 mma) + bias + residual -> mid (fp32)
    gemm_f16_kernel<2><<<dim3(DM / 128, ROWS / 128), 256, SMEM_G>>>(z16, wo, b_O, resid_pre,
                                                                    mid, DM, DM);
    // 5) LN2 -> fp16
    layernorm_kernel<<<ROWS, 256>>>(mid, ln2w, ln2b, x16);
    // 6) MLP in + bias + GELU (fp16 mma) -> fp16 hidden
    gemm_f16_kernel<1><<<dim3(DMLP / 128, ROWS / 128), 256, SMEM_G>>>(x16, win, b_in, nullptr,
                                                                      h16, DMLP, DM);
    // 7) MLP out (fp16 mma) + bias + residual -> out (fp32)
    gemm_f16_kernel<2><<<dim3(DM / 128, ROWS / 128), 256, SMEM_G>>>(h16, wout, b_out, mid,
                                                                    out, DM, DMLP);
}

// round 17
// speedup vs baseline: 1.5708x; 1.0156x over previous
#include <cuda_runtime.h>
#include <cuda_fp16.h>
#include <math.h>
#include <stdint.h>

#define ROWS  8192          // B*S
#define DM    768
#define DMLP  3072
#define QKVN  2304
#define NHEAD 12
#define DHEAD 64
#define SEQ   1024
#define NBH   96            // B * NHEAD

// Q pre-scale: 1/sqrt(64) * log2(e)  -> scores land in log2 domain
#define QSCALE 0.1803368801111204f

// ---------------- scratch (device globals; no allocation allowed) ----------------
__device__ __half g_x16[ROWS * DM];          // LN1 / LN2 out (fp16, reused sequentially)
__device__ __half g_z16[ROWS * DM];          // attention out (fp16)
__device__ float  g_mid[ROWS * DM];
__device__ __half g_h16[ROWS * DMLP];        // MLP hidden (fp16)
__device__ __half g_wqkv[QKVN * DM];         // [N=2304][K=768] fp16
__device__ __half g_wo[DM * DM];             // [N=768][K=768] fp16
__device__ __half g_win[DMLP * DM];          // [N=3072][K=768] fp16
__device__ __half g_wout[DM * DMLP];         // [N=768][K=3072] fp16
__device__ float  g_bqkv[QKVN];
__device__ __half g_q16[NBH * SEQ * DHEAD];  // [b,h,s,d], pre-scaled QSCALE
__device__ __half g_k16[NBH * SEQ * DHEAD];
__device__ __half g_v16[NBH * SEQ * DHEAD];

// ---------------- helpers ----------------
__device__ __forceinline__ uint32_t smem_to_u32(const void* p) {
    uint32_t a;
    asm("{ .reg .u64 t; cvta.to.shared.u64 t, %1; cvt.u32.u64 %0, t; }" : "=r"(a) : "l"(p));
    return a;
}
__device__ __forceinline__ void cp_async16(uint32_t dst, const void* src) {
    asm volatile("cp.async.cg.shared.global [%0], [%1], 16;\n" :: "r"(dst), "l"(src));
}
#define CP_COMMIT() asm volatile("cp.async.commit_group;\n" ::: "memory")
#define CP_WAIT(n)  asm volatile("cp.async.wait_group %0;\n" :: "n"(n) : "memory")

__device__ __forceinline__ void ldsm_x4(uint32_t& r0, uint32_t& r1, uint32_t& r2, uint32_t& r3,
                                        uint32_t addr) {
    asm volatile("ldmatrix.sync.aligned.m8n8.x4.shared.b16 {%0,%1,%2,%3}, [%4];"
                 : "=r"(r0), "=r"(r1), "=r"(r2), "=r"(r3) : "r"(addr));
}
__device__ __forceinline__ void ldsm_x4_trans(uint32_t& r0, uint32_t& r1, uint32_t& r2,
                                              uint32_t& r3, uint32_t addr) {
    asm volatile("ldmatrix.sync.aligned.m8n8.x4.trans.shared.b16 {%0,%1,%2,%3}, [%4];"
                 : "=r"(r0), "=r"(r1), "=r"(r2), "=r"(r3) : "r"(addr));
}
__device__ __forceinline__ void mma_f16(float* c, const uint32_t* a, uint32_t b0, uint32_t b1) {
    asm volatile(
        "mma.sync.aligned.m16n8k16.row.col.f32.f16.f16.f32 "
        "{%0,%1,%2,%3}, {%4,%5,%6,%7}, {%8,%9}, {%0,%1,%2,%3};"
        : "+f"(c[0]), "+f"(c[1]), "+f"(c[2]), "+f"(c[3])
        : "r"(a[0]), "r"(a[1]), "r"(a[2]), "r"(a[3]), "r"(b0), "r"(b1));
}
__device__ __forceinline__ uint32_t pack_h2(float a, float b) {
    __half2 p = __floats2half2_rn(a, b);
    return *(uint32_t*)&p;
}
__device__ __forceinline__ float gelu_new_f(float x) {
    float x3 = x * x * x;
    float t  = tanhf(0.7978845608028654f * (x + 0.044715f * x3));
    return 0.5f * x * (1.0f + t);
}

// ---------------- fused prologue: LN1 + pack_wqkv + 3 weight transposes ----------------
#define NB_LN    ROWS
#define NB_PACK  ((QKVN * DM + 255) / 256)            // 6912
#define NB_TWO   ((DM / 32) * (DM / 32))              // 576
#define NB_TWIN  ((DMLP / 32) * (DM / 32))            // 2304
#define NB_TWOUT ((DM / 32) * (DMLP / 32))            // 2304
#define NB_PREP  (NB_LN + NB_PACK + NB_TWO + NB_TWIN + NB_TWOUT)

__global__ void prep_kernel(const float* __restrict__ resid_pre,
                            const float* __restrict__ ln1w, const float* __restrict__ ln1b,
                            const float* __restrict__ WQ, const float* __restrict__ WK,
                            const float* __restrict__ WV, const float* __restrict__ bQ,
                            const float* __restrict__ bK, const float* __restrict__ bV,
                            const float* __restrict__ WO, const float* __restrict__ Win,
                            const float* __restrict__ Wout) {
    __shared__ float tsh[32][33];
    __shared__ float shs[8], shss[8];
    int blk = blockIdx.x;
    int tid = threadIdx.x;

    if (blk < NB_LN) {
        int row = blk;
        const float* xr = resid_pre + (size_t)row * DM;
        float v0 = xr[tid], v1 = xr[tid + 256], v2 = xr[tid + 512];
        float s  = v0 + v1 + v2;
        float ss = v0 * v0 + v1 * v1 + v2 * v2;
#pragma unroll
        for (int o = 16; o > 0; o >>= 1) {
            s  += __shfl_xor_sync(0xffffffffu, s, o);
            ss += __shfl_xor_sync(0xffffffffu, ss, o);
        }
        int warp = tid >> 5, lane = tid & 31;
        if (lane == 0) { shs[warp] = s; shss[warp] = ss; }
        __syncthreads();
        if (tid < 32) {
            s  = (lane < 8) ? shs[lane] : 0.f;
            ss = (lane < 8) ? shss[lane] : 0.f;
#pragma unroll
            for (int o = 4; o > 0; o >>= 1) {
                s  += __shfl_xor_sync(0xffffffffu, s, o);
                ss += __shfl_xor_sync(0xffffffffu, ss, o);
            }
            if (lane == 0) { shs[0] = s; shss[0] = ss; }
        }
        __syncthreads();
        s = shs[0]; ss = shss[0];
        float mean = s * (1.f / DM);
        float var  = ss * (1.f / DM) - mean * mean;
        float rstd = rsqrtf(var + 1e-5f);
        __half* yr = g_x16 + (size_t)row * DM;
        yr[tid]       = __float2half((v0 - mean) * rstd * ln1w[tid]       + ln1b[tid]);
        yr[tid + 256] = __float2half((v1 - mean) * rstd * ln1w[tid + 256] + ln1b[tid + 256]);
        yr[tid + 512] = __float2half((v2 - mean) * rstd * ln1w[tid + 512] + ln1b[tid + 512]);
        return;
    }
    blk -= NB_LN;

    if (blk < NB_PACK) {
        int idx = blk * 256 + tid;
        if (idx < QKVN * DM) {
            int j = idx / DM;
            int d = idx - j * DM;
            int which = j / DM;
            int jj = j - which * DM;
            int h = jj >> 6, e = jj & 63;
            const float* W = (which == 0) ? WQ : (which == 1) ? WK : WV;
            g_wqkv[idx] = __float2half(W[(h * DM + d) * DHEAD + e]);
        }
        if (idx < QKVN) {
            g_bqkv[idx] = (idx < DM) ? bQ[idx] : (idx < 2 * DM) ? bK[idx - DM]
                                                                : bV[idx - 2 * DM];
        }
        return;
    }
    blk -= NB_PACK;

    const float* in;
    __half* outp;
    int R, C;
    if (blk < NB_TWO)          { in = WO;   outp = g_wo;   R = DM;   C = DM; }
    else if ((blk -= NB_TWO) < NB_TWIN) { in = Win;  outp = g_win;  R = DM;   C = DMLP; }
    else { blk -= NB_TWIN;       in = Wout; outp = g_wout; R = DMLP; C = DM; }
    int nbx = C / 32;
    int bx = (blk % nbx) * 32, by = (blk / nbx) * 32;
    int x = tid & 31, y = tid >> 5;
#pragma unroll
    for (int i = 0; i < 32; i += 8)
        tsh[y + i][x] = in[(size_t)(by + y + i) * C + bx + x];
    __syncthreads();
#pragma unroll
    for (int i = 0; i < 32; i += 8)
        outp[(size_t)(bx + y + i) * R + by + x] = __float2half(tsh[x][y + i]);
}

// ---------------- LayerNorm (emits fp16) — used for LN2 ----------------
__global__ void layernorm_kernel(const float* __restrict__ x, const float* __restrict__ w,
                                 const float* __restrict__ b, __half* __restrict__ yp) {
    int row = blockIdx.x;
    int tid = threadIdx.x;
    const float* xr = x + (size_t)row * DM;
    float v0 = xr[tid], v1 = xr[tid + 256], v2 = xr[tid + 512];
    float s  = v0 + v1 + v2;
    float ss = v0 * v0 + v1 * v1 + v2 * v2;
#pragma unroll
    for (int o = 16; o > 0; o >>= 1) {
        s  += __shfl_xor_sync(0xffffffffu, s, o);
        ss += __shfl_xor_sync(0xffffffffu, ss, o);
    }
    __shared__ float shs[8], shss[8];
    int warp = tid >> 5, lane = tid & 31;
    if (lane == 0) { shs[warp] = s; shss[warp] = ss; }
    __syncthreads();
    if (tid < 32) {
        s  = (lane < 8) ? shs[lane] : 0.f;
        ss = (lane < 8) ? shss[lane] : 0.f;
#pragma unroll
        for (int o = 4; o > 0; o >>= 1) {
            s  += __shfl_xor_sync(0xffffffffu, s, o);
            ss += __shfl_xor_sync(0xffffffffu, ss, o);
        }
        if (lane == 0) { shs[0] = s; shss[0] = ss; }
    }
    __syncthreads();
    s = shs[0]; ss = shss[0];
    float mean = s * (1.f / DM);
    float var  = ss * (1.f / DM) - mean * mean;
    float rstd = rsqrtf(var + 1e-5f);
    __half* yr = yp + (size_t)row * DM;
    yr[tid]       = __float2half((v0 - mean) * rstd * w[tid]       + b[tid]);
    yr[tid + 256] = __float2half((v1 - mean) * rstd * w[tid + 256] + b[tid + 256]);
    yr[tid + 512] = __float2half((v2 - mean) * rstd * w[tid + 512] + b[tid + 512]);
}

#define STG_BYTES 32768   // A 16KB + B 16KB per stage (K=64 fp16)

// ---------------- fp16 HMMA GEMM: C[M,N] = A[M,K] x B[N,K]^T ----------------
// 128x128 CTA tile, 128 threads = 4 warps (2x2), warp tile 64x64,
// K=64/stage, 2 stages (64KB), 2 CTA/SM. Bigger warp tiles cut smem ldsm
// traffic from 96KB to 64KB per stage per CTA (smem-BW was co-binding).
// EPI: 1 = fp16 out +bias+GELU;  2 = fp32 out +bias+residual;
//      3 = QKV split to fp16 g_q16/g_k16/g_v16 (Q scaled QSCALE)
template <int EPI>
__global__ __launch_bounds__(128, 2) void gemm_f16_kernel(
    const __half* __restrict__ A, const __half* __restrict__ B,
    const float* __restrict__ bias, const float* __restrict__ Rres,
    void* __restrict__ Cout, int N, int K) {
    extern __shared__ char smem[];
    int tid = threadIdx.x, lane = tid & 31, wid = tid >> 5;
    int bx = blockIdx.x, by = blockIdx.y;
    int warp_m = (wid & 1) * 64;
    int warp_n = (wid >> 1) * 64;

    const __half* Ab = A + (size_t)(by * 128) * K;
    const __half* Bb = B + (size_t)(bx * 128) * K;
    uint32_t sbase = smem_to_u32(smem);

    float c[4][8][4];
#pragma unroll
    for (int i = 0; i < 4; i++)
#pragma unroll
        for (int j = 0; j < 8; j++)
#pragma unroll
            for (int k = 0; k < 4; k++) c[i][j][k] = 0.f;

    int T = K >> 6;

    auto load_stage = [&](int s, int kt) {
        uint32_t dstA = sbase + s * STG_BYTES;
        uint32_t dstB = dstA + 16384;
        const __half* Ag = Ab + kt * 64;
        const __half* Bg = Bb + kt * 64;
#pragma unroll
        for (int i = 0; i < 8; i++) {
            int idx = tid + i * 128;
            int r = idx >> 3, cc = idx & 7;
            uint32_t off = (uint32_t)(r * 128 + ((cc ^ (r & 7)) * 16));
            cp_async16(dstA + off, Ag + (size_t)r * K + cc * 8);
            cp_async16(dstB + off, Bg + (size_t)r * K + cc * 8);
        }
        CP_COMMIT();
    };

    load_stage(0, 0);
    load_stage(1, 1);

    int l7 = lane & 7;
    int a_r = ((lane >> 3) & 1) * 8 + l7;
    int a_k = lane >> 4;
    int b_r = (lane >> 4) * 8 + l7;
    int b_k = (lane >> 3) & 1;

    for (int t = 0; t < T; t++) {
        if (t + 1 < T) { CP_WAIT(1); } else { CP_WAIT(0); }
        __syncthreads();

        uint32_t sA = sbase + (t & 1) * STG_BYTES;
        uint32_t sB = sA + 16384;
#pragma unroll
        for (int ks = 0; ks < 4; ks++) {
            uint32_t a[4][4];
#pragma unroll
            for (int i = 0; i < 4; i++) {
                int row = warp_m + i * 16 + a_r;
                uint32_t addr = sA + row * 128 + (((ks * 2 + a_k) ^ l7) * 16);
                ldsm_x4(a[i][0], a[i][1], a[i][2], a[i][3], addr);
            }
            uint32_t b[4][4];
#pragma unroll
            for (int j = 0; j < 4; j++) {
                int row = warp_n + j * 16 + b_r;
                uint32_t addr = sB + row * 128 + (((ks * 2 + b_k) ^ l7) * 16);
                ldsm_x4(b[j][0], b[j][1], b[j][2], b[j][3], addr);
            }
#pragma unroll
            for (int i = 0; i < 4; i++)
#pragma unroll
                for (int jj = 0; jj < 8; jj++)
                    mma_f16(c[i][jj], a[i], b[jj >> 1][(jj & 1) * 2],
                            b[jj >> 1][(jj & 1) * 2 + 1]);
        }
        __syncthreads();
        if (t + 2 < T) load_stage(t & 1, t + 2);
    }

    int quad = lane >> 2, tc2 = (lane & 3) * 2;
#pragma unroll
    for (int i = 0; i < 4; i++) {
#pragma unroll
        for (int jj = 0; jj < 8; jj++) {
            int row0 = by * 128 + warp_m + i * 16 + quad;
            int col  = bx * 128 + warp_n + jj * 8 + tc2;
            float bb0 = bias[col], bb1 = bias[col + 1];
            float v0 = c[i][jj][0] + bb0, v1 = c[i][jj][1] + bb1;
            float v2 = c[i][jj][2] + bb0, v3 = c[i][jj][3] + bb1;
            if (EPI == 3) {
                int which = col / DM;
                int rem = col - which * DM;
                int h = rem >> 6, e = rem & 63;
                __half* dsth = (which == 0) ? g_q16 : (which == 1) ? g_k16 : g_v16;
                float sc = (which == 0) ? QSCALE : 1.0f;
#pragma unroll
                for (int rr = 0; rr < 2; rr++) {
                    int rg = row0 + rr * 8;
                    int b_ = rg >> 10, s_ = rg & 1023;
                    size_t di = ((size_t)(b_ * NHEAD + h) * SEQ + s_) * DHEAD + e;
                    float x0 = (rr ? v2 : v0) * sc, x1 = (rr ? v3 : v1) * sc;
                    *(uint32_t*)(dsth + di) = pack_h2(x0, x1);
                }
            } else if (EPI == 1) {
                v0 = gelu_new_f(v0); v1 = gelu_new_f(v1);
                v2 = gelu_new_f(v2); v3 = gelu_new_f(v3);
                __half* Ch = (__half*)Cout;
                *(uint32_t*)(Ch + (size_t)row0 * N + col)       = pack_h2(v0, v1);
                *(uint32_t*)(Ch + (size_t)(row0 + 8) * N + col) = pack_h2(v2, v3);
            } else {
                const float2 r0 = *(const float2*)(Rres + (size_t)row0 * N + col);
                const float2 r1 = *(const float2*)(Rres + (size_t)(row0 + 8) * N + col);
                v0 += r0.x; v1 += r0.y; v2 += r1.x; v3 += r1.y;
                float* Cf = (float*)Cout;
                *(float2*)(Cf + (size_t)row0 * N + col)       = make_float2(v0, v1);
                *(float2*)(Cf + (size_t)(row0 + 8) * N + col) = make_float2(v2, v3);
            }
        }
    }
}

// ---------------- FA2 fp16 attention: 128-row q-tiles, log2-domain softmax ----------------
// 3-stage KV pipeline (two tiles in flight), longest q-tiles launched first.
__global__ __launch_bounds__(256) void attn_kernel(__half* __restrict__ z) {
    extern __shared__ char sm[];                 // Q 16KB | {K 8KB, V 8KB} x3 stages
    int qt = gridDim.x - 1 - blockIdx.x;         // longest-first scheduling
    int bh = blockIdx.y;
    int b = bh / NHEAD, h = bh - b * NHEAD;
    int tid = threadIdx.x, lane = tid & 31, w = tid >> 5;

    uint32_t sQ = smem_to_u32(sm);
    const __half* Qg = g_q16 + ((size_t)bh * SEQ + qt * 128) * DHEAD;
    const __half* Kg = g_k16 + (size_t)bh * SEQ * DHEAD;
    const __half* Vg = g_v16 + (size_t)bh * SEQ * DHEAD;

    {
#pragma unroll
        for (int i = 0; i < 4; i++) {
            int idx = tid + i * 256;
            int r = idx >> 3, cc = idx & 7;
            uint32_t off = (uint32_t)(r * 128 + ((cc ^ (r & 7)) << 4));
            cp_async16(sQ + off, Qg + (size_t)r * DHEAD + cc * 8);
        }
        CP_COMMIT();
    }
    auto load_kv = [&](int s, int jt) {
        uint32_t bK = sQ + 16384 + s * 16384;
        const __half* Ksrc = Kg + (size_t)jt * 64 * DHEAD;
        const __half* Vsrc = Vg + (size_t)jt * 64 * DHEAD;
#pragma unroll
        for (int i = 0; i < 2; i++) {
            int idx = tid + i * 256;
            int r = idx >> 3, cc = idx & 7;
            uint32_t off = (uint32_t)(r * 128 + ((cc ^ (r & 7)) << 4));
            cp_async16(bK + off, Ksrc + (size_t)r * DHEAD + cc * 8);
            cp_async16(bK + 8192 + off, Vsrc + (size_t)r * DHEAD + cc * 8);
        }
        CP_COMMIT();
    };

    int ntile = 2 * qt + 2;
    load_kv(0, 0);
    if (ntile > 1) load_kv(1, 1);
    CP_WAIT(1);
    __syncthreads();

    int l7 = lane & 7, lg = lane >> 3;
    uint32_t qa[4][4];
#pragma unroll
    for (int ks = 0; ks < 4; ks++) {
        int row = w * 16 + ((lg & 1) << 3) + l7;
        int chunk = ks * 2 + (lg >> 1);
        uint32_t addr = sQ + row * 128 + ((chunk ^ (row & 7)) << 4);
        ldsm_x4(qa[ks][0], qa[ks][1], qa[ks][2], qa[ks][3], addr);
    }

    int quad = lane >> 2, tc2 = (lane & 3) * 2;
    int wrow = qt * 128 + w * 16;
    float acc[8][4];
#pragma unroll
    for (int j = 0; j < 8; j++)
#pragma unroll
        for (int v = 0; v < 4; v++) acc[j][v] = 0.f;
    float m0 = -INFINITY, m1 = -INFINITY, l0 = 0.f, l1 = 0.f;

    for (int jt = 0; jt < ntile; jt++) {
        if (jt + 2 < ntile) { load_kv((jt + 2) % 3, jt + 2); CP_WAIT(2); }
        else if (jt + 1 < ntile) { CP_WAIT(1); }
        else                     { CP_WAIT(0); }
        __syncthreads();

        if (jt * 64 <= wrow + 15) {
            uint32_t sK = sQ + 16384 + (jt % 3) * 16384;
            uint32_t sV = sK + 8192;

            float c[8][4];
#pragma unroll
            for (int j = 0; j < 8; j++)
#pragma unroll
                for (int v = 0; v < 4; v++) c[j][v] = 0.f;
#pragma unroll
            for (int ks = 0; ks < 4; ks++) {
                uint32_t kb[4][4];
#pragma unroll
                for (int g = 0; g < 4; g++) {
                    int row = g * 16 + (lg >> 1) * 8 + l7;
                    int chunk = ks * 2 + (lg & 1);
                    uint32_t addr = sK + row * 128 + ((chunk ^ (row & 7)) << 4);
                    ldsm_x4(kb[g][0], kb[g][1], kb[g][2], kb[g][3], addr);
                }
#pragma unroll
                for (int j = 0; j < 8; j++)
                    mma_f16(c[j], qa[ks], kb[j >> 1][(j & 1) * 2],
                            kb[j >> 1][(j & 1) * 2 + 1]);
            }

            if ((jt + 1) * 64 - 1 > wrow) {
                int r0 = wrow + quad;
                int kbase = jt * 64;
#pragma unroll
                for (int j = 0; j < 8; j++) {
                    int kc = kbase + j * 8 + tc2;
                    if (kc > r0)     c[j][0] = -INFINITY;
                    if (kc + 1 > r0) c[j][1] = -INFINITY;
                    if (kc > r0 + 8)     c[j][2] = -INFINITY;
                    if (kc + 1 > r0 + 8) c[j][3] = -INFINITY;
                }
            }

            float mx0 = -INFINITY, mx1 = -INFINITY;
#pragma unroll
            for (int j = 0; j < 8; j++) {
                mx0 = fmaxf(mx0, fmaxf(c[j][0], c[j][1]));
                mx1 = fmaxf(mx1, fmaxf(c[j][2], c[j][3]));
            }
            mx0 = fmaxf(mx0, __shfl_xor_sync(0xffffffffu, mx0, 1));
            mx0 = fmaxf(mx0, __shfl_xor_sync(0xffffffffu, mx0, 2));
            mx1 = fmaxf(mx1, __shfl_xor_sync(0xffffffffu, mx1, 1));
            mx1 = fmaxf(mx1, __shfl_xor_sync(0xffffffffu, mx1, 2));
            float mn0 = fmaxf(m0, mx0), mn1 = fmaxf(m1, mx1);
            float corr0 = exp2f(m0 - mn0), corr1 = exp2f(m1 - mn1);
            l0 *= corr0; l1 *= corr1;
#pragma unroll
            for (int j = 0; j < 8; j++) {
                c[j][0] = exp2f(c[j][0] - mn0);
                c[j][1] = exp2f(c[j][1] - mn0);
                c[j][2] = exp2f(c[j][2] - mn1);
                c[j][3] = exp2f(c[j][3] - mn1);
                l0 += c[j][0] + c[j][1];
                l1 += c[j][2] + c[j][3];
#pragma unroll
                for (int v = 0; v < 4; v++)
                    acc[j][v] *= (v < 2) ? corr0 : corr1;
            }
            m0 = mn0; m1 = mn1;

#pragma unroll
            for (int t = 0; t < 4; t++) {
                uint32_t pa[4];
                pa[0] = pack_h2(c[2 * t][0], c[2 * t][1]);
                pa[1] = pack_h2(c[2 * t][2], c[2 * t][3]);
                pa[2] = pack_h2(c[2 * t + 1][0], c[2 * t + 1][1]);
                pa[3] = pack_h2(c[2 * t + 1][2], c[2 * t + 1][3]);
#pragma unroll
                for (int nb = 0; nb < 4; nb++) {
                    uint32_t vb[4];
                    int key = t * 16 + ((lg & 1) << 3) + l7;
                    int chunk = nb * 2 + (lg >> 1);
                    uint32_t addr = sV + key * 128 + ((chunk ^ (key & 7)) << 4);
                    ldsm_x4_trans(vb[0], vb[1], vb[2], vb[3], addr);
                    mma_f16(acc[nb * 2],     pa, vb[0], vb[1]);
                    mma_f16(acc[nb * 2 + 1], pa, vb[2], vb[3]);
                }
            }
        }
        __syncthreads();
    }

    l0 += __shfl_xor_sync(0xffffffffu, l0, 1);
    l0 += __shfl_xor_sync(0xffffffffu, l0, 2);
    l1 += __shfl_xor_sync(0xffffffffu, l1, 1);
    l1 += __shfl_xor_sync(0xffffffffu, l1, 2);
    float inv0 = 1.f / l0, inv1 = 1.f / l1;
    int r0g = b * SEQ + qt * 128 + w * 16 + quad;
#pragma unroll
    for (int j = 0; j < 8; j++) {
        int col = h * 64 + j * 8 + tc2;
        *(uint32_t*)(z + (size_t)r0g * DM + col) = pack_h2(acc[j][0] * inv0, acc[j][1] * inv0);
        *(uint32_t*)(z + (size_t)(r0g + 8) * DM + col) =
            pack_h2(acc[j][2] * inv1, acc[j][3] * inv1);
    }
}

// ---------------- launch ----------------
extern "C" void kernel_launch(void* const* d_in, const int* in_sizes, int n_in,
                              void* d_out, int out_size) {
    const float* resid_pre = (const float*)d_in[0];
    const float* W_Q  = (const float*)d_in[1];
    const float* W_K  = (const float*)d_in[2];
    const float* W_V  = (const float*)d_in[3];
    const float* W_O  = (const float*)d_in[4];
    const float* b_Q  = (const float*)d_in[5];
    const float* b_K  = (const float*)d_in[6];
    const float* b_V  = (const float*)d_in[7];
    const float* b_O  = (const float*)d_in[8];
    const float* ln1w = (const float*)d_in[9];
    const float* ln1b = (const float*)d_in[10];
    const float* ln2w = (const float*)d_in[11];
    const float* ln2b = (const float*)d_in[12];
    const float* W_in  = (const float*)d_in[13];
    const float* b_in  = (const float*)d_in[14];
    const float* W_out = (const float*)d_in[15];
    const float* b_out = (const float*)d_in[16];
    float* out = (float*)d_out;

    __half *x16, *z16, *h16, *wqkv, *wo, *win, *wout;
    float *mid, *bqkv;
    cudaGetSymbolAddress((void**)&x16,  g_x16);
    cudaGetSymbolAddress((void**)&z16,  g_z16);
    cudaGetSymbolAddress((void**)&h16,  g_h16);
    cudaGetSymbolAddress((void**)&mid,  g_mid);
    cudaGetSymbolAddress((void**)&wqkv, g_wqkv);
    cudaGetSymbolAddress((void**)&wo,   g_wo);
    cudaGetSymbolAddress((void**)&win,  g_win);
    cudaGetSymbolAddress((void**)&wout, g_wout);
    cudaGetSymbolAddress((void**)&bqkv, g_bqkv);

    const int SMEM_G = 2 * STG_BYTES;           // 64KB, 2 CTA/SM
    const int SMEM_A = 16384 + 3 * 16384;       // 64KB attention (3-stage KV)
    cudaFuncSetAttribute(gemm_f16_kernel<1>, cudaFuncAttributeMaxDynamicSharedMemorySize, SMEM_G);
    cudaFuncSetAttribute(gemm_f16_kernel<2>, cudaFuncAttributeMaxDynamicSharedMemorySize, SMEM_G);
    cudaFuncSetAttribute(gemm_f16_kernel<3>, cudaFuncAttributeMaxDynamicSharedMemorySize, SMEM_G);
    cudaFuncSetAttribute(attn_kernel, cudaFuncAttributeMaxDynamicSharedMemorySize, SMEM_A);

    // 1) fused prologue: LN1 + all weight packing in ONE launch
    prep_kernel<<<NB_PREP, 256>>>(resid_pre, ln1w, ln1b, W_Q, W_K, W_V, b_Q, b_K, b_V,
                                  W_O, W_in, W_out);
    // 2) fused QKV projection (fp16 mma) -> fp16 Q/K/V [b,h,s,d], Q in log2-softmax scale
    gemm_f16_kernel<3><<<dim3(QKVN / 128, ROWS / 128), 128, SMEM_G>>>(x16, wqkv, bqkv,
                                                                      nullptr, nullptr, QKVN, DM);
    // 3) tensor-core causal attention -> z (fp16)
    attn_kernel<<<dim3(SEQ / 128, NBH), 256, SMEM_A>>>(z16);
    // 4) O projection (fp16 mma) + bias + residual -> mid (fp32)
    gemm_f16_kernel<2><<<dim3(DM / 128, ROWS / 128), 128, SMEM_G>>>(z16, wo, b_O, resid_pre,
                                                                    mid, DM, DM);
    // 5) LN2 -> fp16
    layernorm_kernel<<<ROWS, 256>>>(mid, ln2w, ln2b, x16);
    // 6) MLP in + bias + GELU (fp16 mma) -> fp16 hidden
    gemm_f16_kernel<1><<<dim3(DMLP / 128, ROWS / 128), 128, SMEM_G>>>(x16, win, b_in, nullptr,
                                                                      h16, DMLP, DM);
    // 7) MLP out (fp16 mma) + bias + residual -> out (fp32)
    gemm_f16_kernel<2><<<dim3(DM / 128, ROWS / 128), 128, SMEM_G>>>(h16, wout, b_out, mid,
                                                                    out, DM, DMLP);
}